// round 9
// baseline (speedup 1.0000x reference)
#include <cuda_runtime.h>

// SqueezeSeg Recurrent CRF — fused per-iteration kernel, sm_103a. Round 3.
// B=16, C=4, H=64, W=512, 3x5 neighborhood (14 neighbors), 3 iterations.
//
// Changes vs R2:
//  - 2 W-pixels per thread: bf loads become LDG.64, stencil rows load the
//    6-column union of u/m once per row (9 LDS.128 + 9 LDS.32 per pixel
//    instead of 14+14), outputs become STG.64.
//  - Row-structured fully-unrolled stencil (3 rows x 5 taps, center skipped).
//
// Math notes (verified vs reference):
//  - ANG_THETA_A == BILATERAL_THETA_A => g_ang == g_bi => bi_ang == ang.
//  - compat = ones - eye => ang2[o] = 0.02*(sum_c ang[c] - ang[o]), bi2 0.10.

#define BATCH 16
#define NC 4
#define HH 64
#define WW 512
#define PLANE (HH*WW)

#define TH 8          // tile height (pixel rows per block)
#define TW 64         // tile width  (pixels per block row)
#define TXN 32        // threads in x; each handles 2 W-pixels
#define SH (TH + 2)   // halo 1 in H
#define SW (TW + 4)   // halo 2 in W
#define NTHREADS (TXN * TH)   // 256

__device__ float g_scratchA[BATCH * NC * PLANE];
__device__ float g_scratchB[BATCH * NC * PLANE];

__global__ __launch_bounds__(NTHREADS)
void crf_iter_kernel(const float* __restrict__ x,
                     const float* __restrict__ bf,     // [B,14,H,W]
                     const float* __restrict__ mask,   // [B,H,W]
                     float* __restrict__ out)          // [B,4,H,W]
{
    __shared__ float4 s_u[SH][SW];
    __shared__ float  s_m[SH][SW];

    const int b  = blockIdx.z;
    const int h0 = blockIdx.y * TH;
    const int w0 = blockIdx.x * TW;
    const int tx = threadIdx.x;   // 0..31 -> pixel pair
    const int ty = threadIdx.y;   // 0..7
    const int tid = ty * TXN + tx;

    const float* xb = x    + (size_t)b * NC * PLANE;
    const float* mb = mask + (size_t)b * PLANE;

    // ---- Phase 1: cooperative load + per-pixel softmax into smem (tile+halo)
    #pragma unroll
    for (int i = tid; i < SH * SW; i += NTHREADS) {
        const int sh = i / SW;
        const int sw = i % SW;
        const int h = h0 + sh - 1;
        const int w = w0 + sw - 2;
        float4 u = make_float4(0.f, 0.f, 0.f, 0.f);
        float m = 0.f;
        if (h >= 0 && h < HH && w >= 0 && w < WW) {
            const int off = h * WW + w;
            const float a0 = xb[0 * PLANE + off];
            const float a1 = xb[1 * PLANE + off];
            const float a2 = xb[2 * PLANE + off];
            const float a3 = xb[3 * PLANE + off];
            const float mx = fmaxf(fmaxf(a0, a1), fmaxf(a2, a3));
            u.x = __expf(a0 - mx);
            u.y = __expf(a1 - mx);
            u.z = __expf(a2 - mx);
            u.w = __expf(a3 - mx);
            const float inv = 1.0f / (u.x + u.y + u.z + u.w);
            u.x *= inv; u.y *= inv; u.z *= inv; u.w *= inv;
            m = mb[off];
        }
        s_u[sh][sw] = u;
        s_m[sh][sw] = m;
    }
    __syncthreads();

    // ---- Phase 2: stencil, 2 W-pixels per thread
    const int h  = h0 + ty;
    const int wp = w0 + 2 * tx;          // even pixel of the pair
    const int off = h * WW + wp;
    const int cb = 2 * tx;               // smem column base (j=0 -> w = wp-2)

    // Gaussian weights: d2 in {1,2,4,5}, denom 2*0.9^2 = 1.62
    const float inv_den = 1.0f / 1.62f;
    const float e1 = __expf(-1.0f * inv_den);
    const float e2 = __expf(-2.0f * inv_den);
    const float e4 = __expf(-4.0f * inv_den);
    const float e5 = __expf(-5.0f * inv_den);
    // weight rows: type A (dz=0,2): [e5,e2,e1,e2,e5]; type B (dz=1): [e4,e1,0,e1,e4]
    const float wA[5] = {e5, e2, e1, e2, e5};
    const float wB[5] = {e4, e1, 0.f, e1, e4};

    const float* bfp = bf + (size_t)b * 14 * PLANE + off;

    float4 ang0  = make_float4(0.f, 0.f, 0.f, 0.f);
    float4 ang1  = make_float4(0.f, 0.f, 0.f, 0.f);
    float4 cond0 = make_float4(0.f, 0.f, 0.f, 0.f);
    float4 cond1 = make_float4(0.f, 0.f, 0.f, 0.f);

    // k index of (dz, da): dz=0 -> 0..4 ; dz=1 -> 5,6,-,7,8 ; dz=2 -> 9..13
    #pragma unroll
    for (int r = 0; r < 3; ++r) {                 // stencil row, sh = ty + r
        const int sh = ty + r;
        // load the 6-column union once
        float4 uu[6];
        float  mm[6];
        #pragma unroll
        for (int j = 0; j < 6; ++j) {
            uu[j] = s_u[sh][cb + j];
            mm[j] = s_m[sh][cb + j];
        }
        const bool mid = (r == 1);
        #pragma unroll
        for (int da = 0; da < 5; ++da) {
            if (mid && da == 2) continue;         // center excluded
            const int k = mid ? (5 + da - (da > 2 ? 1 : 0))
                              : (r == 0 ? da : 9 + da);
            const float g = mid ? wB[da] : wA[da];
            const float2 bf2 = *(const float2*)(bfp + k * PLANE);
            // pixel 0 uses column da, pixel 1 uses column da+1
            const float4 ua = uu[da];
            const float4 ub = uu[da + 1];
            const float bm0 = bf2.x * mm[da];
            const float bm1 = bf2.y * mm[da + 1];
            ang0.x = fmaf(g, ua.x, ang0.x);  ang1.x = fmaf(g, ub.x, ang1.x);
            ang0.y = fmaf(g, ua.y, ang0.y);  ang1.y = fmaf(g, ub.y, ang1.y);
            ang0.z = fmaf(g, ua.z, ang0.z);  ang1.z = fmaf(g, ub.z, ang1.z);
            ang0.w = fmaf(g, ua.w, ang0.w);  ang1.w = fmaf(g, ub.w, ang1.w);
            cond0.x = fmaf(bm0, ua.x, cond0.x);  cond1.x = fmaf(bm1, ub.x, cond1.x);
            cond0.y = fmaf(bm0, ua.y, cond0.y);  cond1.y = fmaf(bm1, ub.y, cond1.y);
            cond0.z = fmaf(bm0, ua.z, cond0.z);  cond1.z = fmaf(bm1, ub.z, cond1.z);
            cond0.w = fmaf(bm0, ua.w, cond0.w);  cond1.w = fmaf(bm1, ub.w, cond1.w);
        }
    }

    // ---- Epilogue
    const float mc0 = s_m[ty + 1][cb + 2];
    const float mc1 = s_m[ty + 1][cb + 3];
    const float4 uc0 = s_u[ty + 1][cb + 2];
    const float4 uc1 = s_u[ty + 1][cb + 3];

    // bi_ang == ang (equal thetas)
    const float b0x = cond0.x * mc0 * ang0.x;
    const float b0y = cond0.y * mc0 * ang0.y;
    const float b0z = cond0.z * mc0 * ang0.z;
    const float b0w = cond0.w * mc0 * ang0.w;
    const float b1x = cond1.x * mc1 * ang1.x;
    const float b1y = cond1.y * mc1 * ang1.y;
    const float b1z = cond1.z * mc1 * ang1.z;
    const float b1w = cond1.w * mc1 * ang1.w;

    const float sa0 = ang0.x + ang0.y + ang0.z + ang0.w;
    const float sa1 = ang1.x + ang1.y + ang1.z + ang1.w;
    const float sb0 = b0x + b0y + b0z + b0w;
    const float sb1 = b1x + b1y + b1z + b1w;

    float* ob = out + (size_t)b * NC * PLANE + off;
    float2 o;
    o.x = uc0.x + 0.02f * (sa0 - ang0.x) + 0.10f * (sb0 - b0x);
    o.y = uc1.x + 0.02f * (sa1 - ang1.x) + 0.10f * (sb1 - b1x);
    *(float2*)(ob + 0 * PLANE) = o;
    o.x = uc0.y + 0.02f * (sa0 - ang0.y) + 0.10f * (sb0 - b0y);
    o.y = uc1.y + 0.02f * (sa1 - ang1.y) + 0.10f * (sb1 - b1y);
    *(float2*)(ob + 1 * PLANE) = o;
    o.x = uc0.z + 0.02f * (sa0 - ang0.z) + 0.10f * (sb0 - b0z);
    o.y = uc1.z + 0.02f * (sa1 - ang1.z) + 0.10f * (sb1 - b1z);
    *(float2*)(ob + 2 * PLANE) = o;
    o.x = uc0.w + 0.02f * (sa0 - ang0.w) + 0.10f * (sb0 - b0w);
    o.y = uc1.w + 0.02f * (sa1 - ang1.w) + 0.10f * (sb1 - b1w);
    *(float2*)(ob + 3 * PLANE) = o;
}

extern "C" void kernel_launch(void* const* d_in, const int* in_sizes, int n_in,
                              void* d_out, int out_size)
{
    const float* x    = (const float*)d_in[0];  // [16,4,64,512]
    const float* bf   = (const float*)d_in[1];  // [16,1,14,64,512]
    const float* mask = (const float*)d_in[2];  // [16,1,64,512]
    float* out = (float*)d_out;

    float* sa = nullptr;
    float* sb = nullptr;
    cudaGetSymbolAddress((void**)&sa, g_scratchA);
    cudaGetSymbolAddress((void**)&sb, g_scratchB);

    dim3 block(TXN, TH, 1);                 // 256 threads, 2 px/thread in W
    dim3 grid(WW / TW, HH / TH, BATCH);     // 8 x 8 x 16 = 1024 blocks

    crf_iter_kernel<<<grid, block>>>(x,  bf, mask, sa);
    crf_iter_kernel<<<grid, block>>>(sa, bf, mask, sb);
    crf_iter_kernel<<<grid, block>>>(sb, bf, mask, out);
}

// round 10
// speedup vs baseline: 1.1452x; 1.1452x over previous
#include <cuda_runtime.h>

// SqueezeSeg Recurrent CRF — fused per-iteration kernel, sm_103a. Round 4.
// B=16, C=4, H=64, W=512, 3x5 neighborhood (14 neighbors), 3 iterations.
//
// R4 = R2 (best: 31.5us, occ 81%, 32 regs) + packed f32x2 math:
//  - accumulators are f32x2 pairs (classes {0,1} and {2,3});
//  - smem float4 unary read as ulonglong2 -> two aligned f32x2 operands free;
//  - fma.rn.f32x2 (Blackwell FFMA2) halves FMA-pipe ops; only {bm,bm}
//    needs a mov.b64 pack per tap; Gaussian weight pairs hoisted.
//
// Math notes (verified vs reference):
//  - ANG_THETA_A == BILATERAL_THETA_A => g_ang == g_bi => bi_ang == ang.
//  - compat = ones - eye => out[o] = unary[o] + 0.02*(sum_ang - ang[o])
//                                   + 0.10*(sum_bi - bi[o]).

#define BATCH 16
#define NC 4
#define HH 64
#define WW 512
#define PLANE (HH*WW)

#define TH 8
#define TW 64
#define SH (TH + 2)   // halo 1 in H
#define SW (TW + 4)   // halo 2 in W
#define NTHREADS (TH * TW)   // 512

typedef unsigned long long u64t;

__device__ __forceinline__ u64t ffma2(u64t a, u64t b, u64t c) {
    u64t d;
    asm("fma.rn.f32x2 %0, %1, %2, %3;" : "=l"(d) : "l"(a), "l"(b), "l"(c));
    return d;
}
__device__ __forceinline__ u64t pack2(float lo, float hi) {
    u64t d;
    asm("mov.b64 %0, {%1, %2};" : "=l"(d) : "f"(lo), "f"(hi));
    return d;
}
__device__ __forceinline__ void unpack2(u64t v, float& lo, float& hi) {
    asm("mov.b64 {%0, %1}, %2;" : "=f"(lo), "=f"(hi) : "l"(v));
}

__device__ float g_scratchA[BATCH * NC * PLANE];
__device__ float g_scratchB[BATCH * NC * PLANE];

__global__ __launch_bounds__(NTHREADS)
void crf_iter_kernel(const float* __restrict__ x,
                     const float* __restrict__ bf,     // [B,14,H,W]
                     const float* __restrict__ mask,   // [B,H,W]
                     float* __restrict__ out)          // [B,4,H,W]
{
    __shared__ float4 s_u[SH][SW];
    __shared__ float  s_m[SH][SW];

    const int b  = blockIdx.z;
    const int h0 = blockIdx.y * TH;
    const int w0 = blockIdx.x * TW;
    const int tx = threadIdx.x;   // 0..63 along W
    const int ty = threadIdx.y;   // 0..7 along H
    const int tid = ty * TW + tx;

    const float* xb = x    + (size_t)b * NC * PLANE;
    const float* mb = mask + (size_t)b * PLANE;

    // ---- Phase 1: cooperative load + per-pixel softmax into smem (tile+halo)
    #pragma unroll
    for (int i = tid; i < SH * SW; i += NTHREADS) {
        const int sh = i / SW;
        const int sw = i % SW;
        const int h = h0 + sh - 1;
        const int w = w0 + sw - 2;
        float4 u = make_float4(0.f, 0.f, 0.f, 0.f);
        float m = 0.f;
        if (h >= 0 && h < HH && w >= 0 && w < WW) {
            const int off = h * WW + w;
            const float a0 = xb[0 * PLANE + off];
            const float a1 = xb[1 * PLANE + off];
            const float a2 = xb[2 * PLANE + off];
            const float a3 = xb[3 * PLANE + off];
            const float mx = fmaxf(fmaxf(a0, a1), fmaxf(a2, a3));
            u.x = __expf(a0 - mx);
            u.y = __expf(a1 - mx);
            u.z = __expf(a2 - mx);
            u.w = __expf(a3 - mx);
            const float inv = 1.0f / (u.x + u.y + u.z + u.w);
            u.x *= inv; u.y *= inv; u.z *= inv; u.w *= inv;
            m = mb[off];
        }
        s_u[sh][sw] = u;
        s_m[sh][sw] = m;
    }
    __syncthreads();

    // ---- Phase 2: stencil (1 px per thread), packed f32x2 accumulation
    const int h = h0 + ty;
    const int w = w0 + tx;
    const int off = h * WW + w;

    // Gaussian weights: d2 in {1,2,4,5}, denom 2*0.9^2 = 1.62
    const float inv_den = 1.0f / 1.62f;
    const float e1 = __expf(-1.0f * inv_den);
    const float e2 = __expf(-2.0f * inv_den);
    const float e4 = __expf(-4.0f * inv_den);
    const float e5 = __expf(-5.0f * inv_den);
    const u64t g2[4] = { pack2(e1, e1), pack2(e2, e2), pack2(e4, e4), pack2(e5, e5) };

    const float* bfp = bf + (size_t)b * 14 * PLANE + off;

    u64t ang_lo  = pack2(0.f, 0.f);   // classes 0,1
    u64t ang_hi  = pack2(0.f, 0.f);   // classes 2,3
    u64t cond_lo = pack2(0.f, 0.f);
    u64t cond_hi = pack2(0.f, 0.f);

    // neighbor offsets (dz, da) of 3x5 kernel, center excluded; d2->g2 index
    const int offz[14] = {0,0,0,0,0, 1,1,1,1, 2,2,2,2,2};
    const int offa[14] = {0,1,2,3,4, 0,1,3,4, 0,1,2,3,4};

    #pragma unroll
    for (int k = 0; k < 14; ++k) {
        const int dz = offz[k];
        const int da = offa[k];
        const int d2 = (dz - 1) * (dz - 1) + (da - 2) * (da - 2);
        const int gi = (d2 == 1) ? 0 : (d2 == 2) ? 1 : (d2 == 4) ? 2 : 3;
        const int sh = ty + dz;
        const int sw = tx + da;
        const ulonglong2 u2 = *reinterpret_cast<const ulonglong2*>(&s_u[sh][sw]);
        const float m  = s_m[sh][sw];
        const float bm = bfp[k * PLANE] * m;
        const u64t bm2 = pack2(bm, bm);
        ang_lo  = ffma2(g2[gi], u2.x, ang_lo);
        ang_hi  = ffma2(g2[gi], u2.y, ang_hi);
        cond_lo = ffma2(bm2,    u2.x, cond_lo);
        cond_hi = ffma2(bm2,    u2.y, cond_hi);
    }

    // ---- Epilogue (scalar)
    float a0, a1, a2, a3, c0, c1, c2, c3;
    unpack2(ang_lo,  a0, a1);
    unpack2(ang_hi,  a2, a3);
    unpack2(cond_lo, c0, c1);
    unpack2(cond_hi, c2, c3);

    const float mc = s_m[ty + 1][tx + 2];
    // bi_ang == ang (equal thetas)
    const float b0 = c0 * mc * a0;
    const float b1 = c1 * mc * a1;
    const float b2 = c2 * mc * a2;
    const float b3 = c3 * mc * a3;

    const float sa = a0 + a1 + a2 + a3;
    const float sb = b0 + b1 + b2 + b3;

    const float4 uc = s_u[ty + 1][tx + 2];
    float* ob = out + (size_t)b * NC * PLANE;
    ob[0 * PLANE + off] = uc.x + 0.02f * (sa - a0) + 0.10f * (sb - b0);
    ob[1 * PLANE + off] = uc.y + 0.02f * (sa - a1) + 0.10f * (sb - b1);
    ob[2 * PLANE + off] = uc.z + 0.02f * (sa - a2) + 0.10f * (sb - b2);
    ob[3 * PLANE + off] = uc.w + 0.02f * (sa - a3) + 0.10f * (sb - b3);
}

extern "C" void kernel_launch(void* const* d_in, const int* in_sizes, int n_in,
                              void* d_out, int out_size)
{
    const float* x    = (const float*)d_in[0];  // [16,4,64,512]
    const float* bf   = (const float*)d_in[1];  // [16,1,14,64,512]
    const float* mask = (const float*)d_in[2];  // [16,1,64,512]
    float* out = (float*)d_out;

    float* sa = nullptr;
    float* sb = nullptr;
    cudaGetSymbolAddress((void**)&sa, g_scratchA);
    cudaGetSymbolAddress((void**)&sb, g_scratchB);

    dim3 block(TW, TH, 1);                  // 512 threads, 1 px/thread
    dim3 grid(WW / TW, HH / TH, BATCH);     // 8 x 8 x 16 = 1024 blocks

    crf_iter_kernel<<<grid, block>>>(x,  bf, mask, sa);
    crf_iter_kernel<<<grid, block>>>(sa, bf, mask, sb);
    crf_iter_kernel<<<grid, block>>>(sb, bf, mask, out);
}